// round 1
// baseline (speedup 1.0000x reference)
#include <cuda_runtime.h>
#include <math.h>

#define HW    8836       // 94*94
#define PER_B 70688      // 8 * HW (dcap * h * w) -- softmax normalization count
#define NPTS  565504     // 8 batches * PER_B
#define EPSS  1e-8f

// u layout: [b][dcap][Dz][c][hw]  => plane index ((b*8+dcap)*8+Dz)*32+c, innermost hw
__device__ float g_u[8 * 8 * 8 * 32 * 8836];   // 579 MB scratch
__device__ float g_M[36 * NPTS];               // per-point 8x8 Gram (upper triangle), SoA
__device__ float g_bq[8 * NPTS];               // routing logits b, SoA
__device__ float g_S1[64];
__device__ float g_S2[64];

__global__ void init_kernel() {
    int t = threadIdx.x;
    if (t < 64) { g_S1[t] = 0.f; g_S2[t] = 0.f; }
}

// ---------------- Conv: 16->256 ch, 3x3 over each (b,Dz) slice ----------------
// block: (32,8) threads; tile: 64 out-channels x 8h x 32w
__global__ __launch_bounds__(256, 2) void conv_kernel(const float* __restrict__ x,
                                                      const float* __restrict__ w) {
    extern __shared__ float sm[];
    float* xs = sm;          // 16 ci * 10 rows * 34 cols = 5440 floats
    float* ws = sm + 5440;   // 144 k * 64 co = 9216 floats

    int tx = threadIdx.x, ty = threadIdx.y;
    int tid = ty * 32 + tx;
    int tile = blockIdx.x;          // 0..35
    int twi = tile % 3, thi = tile / 3;
    int cb = blockIdx.y;            // 0..3 (64-channel group)
    int bd = blockIdx.z;            // 0..63
    int b = bd >> 3, Dz = bd & 7;
    int hBase = thi * 8, wBase = twi * 32;

    const float* xb = x + ((size_t)(b * 16) * 8 + Dz) * 9216;  // + ci*73728 + y*96 + xx
    #pragma unroll 1
    for (int i = tid; i < 5440; i += 256) {
        int ci = i / 340;
        int rem = i - ci * 340;
        int r = rem / 34;
        int cc_ = rem - r * 34;
        int gy = hBase + r, gx = wBase + cc_;
        float v = 0.f;
        if (gy < 96 && gx < 96) v = xb[ci * 73728 + gy * 96 + gx];
        xs[i] = v;
    }
    #pragma unroll 1
    for (int i = tid; i < 9216; i += 256) {
        int k = i >> 6, col = i & 63;
        ws[i] = w[(cb * 64 + col) * 144 + k];   // k = ci*9 + kh*3 + kw
    }
    __syncthreads();

    float acc[64];
    #pragma unroll
    for (int i = 0; i < 64; i++) acc[i] = 0.f;

    #pragma unroll 1
    for (int ci = 0; ci < 16; ci++) {
        #pragma unroll
        for (int kh = 0; kh < 3; kh++)
        #pragma unroll
        for (int kw = 0; kw < 3; kw++) {
            float xv = xs[ci * 340 + (ty + kh) * 34 + tx + kw];
            const float4* wp = (const float4*)(ws + (ci * 9 + kh * 3 + kw) * 64);
            #pragma unroll
            for (int j = 0; j < 16; j++) {
                float4 wv = wp[j];
                acc[4 * j + 0] += wv.x * xv;
                acc[4 * j + 1] += wv.y * xv;
                acc[4 * j + 2] += wv.z * xv;
                acc[4 * j + 3] += wv.w * xv;
            }
        }
    }

    int h = hBase + ty, wc = wBase + tx;
    if (h < 94 && wc < 94) {
        int hw = h * 94 + wc;
        // acc[co_loc], co = cb*64 + co_loc, co = c*8 + dcap  => c = cb*8 + (co_loc>>3), dcap = co_loc&7
        #pragma unroll
        for (int dcap = 0; dcap < 8; dcap++) {
            size_t base = (((size_t)((b * 8 + dcap) * 8 + Dz)) * 32 + cb * 8) * 8836 + hw;
            #pragma unroll
            for (int cl = 0; cl < 8; cl++) {
                g_u[base + (size_t)cl * 8836] = acc[cl * 8 + dcap];
            }
        }
    }
}

// ---------------- block-reduce e[8] and atomicAdd to S[b*8+d] ----------------
__device__ __forceinline__ void blockReduceAtomic(float e[8], int b, float* Sg) {
    __shared__ float red[8][8];
    #pragma unroll
    for (int off = 16; off > 0; off >>= 1)
        #pragma unroll
        for (int d = 0; d < 8; d++) e[d] += __shfl_down_sync(0xffffffffu, e[d], off);
    int lane = threadIdx.x & 31, wp = threadIdx.x >> 5;
    if (lane == 0) {
        #pragma unroll
        for (int d = 0; d < 8; d++) red[wp][d] = e[d];
    }
    __syncthreads();
    if (threadIdx.x < 8) {
        float s = 0.f;
        #pragma unroll
        for (int w_ = 0; w_ < 8; w_++) s += red[w_][threadIdx.x];
        atomicAdd(&Sg[b * 8 + threadIdx.x], s);
    }
}

// ---------------- Pass A: Gram matrix + routing iteration 0 ----------------
__global__ __launch_bounds__(256) void gram_iter0_kernel() {
    int b = blockIdx.y;
    int pl = blockIdx.x * 256 + threadIdx.x;
    bool act = pl < PER_B;
    float e[8];
    if (act) {
        int dcap = pl / 8836;
        int hw = pl - dcap * 8836;
        const float* up = g_u + ((size_t)(b * 8 + dcap) * 256) * 8836 + hw;

        float M[36];
        #pragma unroll
        for (int i = 0; i < 36; i++) M[i] = 0.f;

        #pragma unroll 4
        for (int c = 0; c < 32; c++) {
            float a[8];
            #pragma unroll
            for (int d = 0; d < 8; d++) a[d] = up[(size_t)(d * 32 + c) * 8836];
            int mi = 0;
            #pragma unroll
            for (int d1 = 0; d1 < 8; d1++)
                #pragma unroll
                for (int d2 = d1; d2 < 8; d2++)
                    M[mi++] += a[d1] * a[d2];
        }

        // iteration 0: c = 1/N uniform; everything from M
        float rs[8];
        #pragma unroll
        for (int d = 0; d < 8; d++) rs[d] = 0.f;
        {
            int mi = 0;
            #pragma unroll
            for (int d1 = 0; d1 < 8; d1++)
                #pragma unroll
                for (int d2 = d1; d2 < 8; d2++) {
                    float m = M[mi++];
                    rs[d2] += m;
                    if (d1 != d2) rs[d1] += m;
                }
        }
        float tot = 0.f;
        #pragma unroll
        for (int d = 0; d < 8; d++) tot += rs[d];
        const float invN = 1.0f / 70688.0f;
        float n2 = tot * invN * invN;                      // |s0|^2
        float h0 = (n2 / (1.f + n2)) / sqrtf(n2 + EPSS);   // squash scale

        int p = b * PER_B + pl;
        #pragma unroll
        for (int i = 0; i < 36; i++) g_M[i * NPTS + p] = M[i];
        #pragma unroll
        for (int d = 0; d < 8; d++) {
            float bv = h0 * invN * rs[d];                  // b1 = u . squash(s0)
            g_bq[d * NPTS + p] = bv;
            e[d] = expf(bv);
        }
    } else {
        #pragma unroll
        for (int d = 0; d < 8; d++) e[d] = 0.f;
    }
    blockReduceAtomic(e, b, g_S1);
}

// ---------------- Pass B: routing iteration 1 (M-only) ----------------
__global__ __launch_bounds__(256) void iter1_kernel() {
    int b = blockIdx.y;
    int pl = blockIdx.x * 256 + threadIdx.x;
    bool act = pl < PER_B;
    float e[8];
    if (act) {
        int p = b * PER_B + pl;
        float bl[8], cc[8];
        #pragma unroll
        for (int d = 0; d < 8; d++) {
            bl[d] = g_bq[d * NPTS + p];
            cc[d] = expf(bl[d]) / g_S1[b * 8 + d];
        }
        float t[8];
        #pragma unroll
        for (int d = 0; d < 8; d++) t[d] = 0.f;
        {
            int mi = 0;
            #pragma unroll
            for (int d1 = 0; d1 < 8; d1++)
                #pragma unroll
                for (int d2 = d1; d2 < 8; d2++) {
                    float m = g_M[mi * NPTS + p];
                    t[d2] += m * cc[d1];
                    if (d1 != d2) t[d1] += m * cc[d2];
                    mi++;
                }
        }
        float n2 = 0.f;
        #pragma unroll
        for (int d = 0; d < 8; d++) n2 += cc[d] * t[d];    // cc^T M cc = |s1|^2
        float h1 = (n2 / (1.f + n2)) / sqrtf(n2 + EPSS);
        #pragma unroll
        for (int d = 0; d < 8; d++) {
            float bn = bl[d] + h1 * t[d];                  // b2
            g_bq[d * NPTS + p] = bn;
            e[d] = expf(bn);
        }
    } else {
        #pragma unroll
        for (int d = 0; d < 8; d++) e[d] = 0.f;
    }
    blockReduceAtomic(e, b, g_S2);
}

// ---------------- Pass C: iteration 2 -> final s ----------------
__global__ __launch_bounds__(256) void final_kernel(float* __restrict__ out) {
    int b = blockIdx.y;
    int pl = blockIdx.x * 256 + threadIdx.x;
    if (pl >= PER_B) return;
    int p = b * PER_B + pl;
    float cc[8];
    #pragma unroll
    for (int d = 0; d < 8; d++)
        cc[d] = expf(g_bq[d * NPTS + p]) / g_S2[b * 8 + d];

    int dcap = pl / 8836, hw = pl - dcap * 8836;
    const float* up = g_u + ((size_t)(b * 8 + dcap) * 256) * 8836 + hw;
    #pragma unroll 4
    for (int c = 0; c < 32; c++) {
        float s = 0.f;
        #pragma unroll
        for (int d = 0; d < 8; d++) s += cc[d] * up[(size_t)(d * 32 + c) * 8836];
        out[((size_t)(b * 32 + c) * 8 + dcap) * 8836 + hw] = s;
    }
}

extern "C" void kernel_launch(void* const* d_in, const int* in_sizes, int n_in,
                              void* d_out, int out_size) {
    const float* x = (const float*)d_in[0];
    const float* w = (const float*)d_in[1];
    float* out = (float*)d_out;

    cudaFuncSetAttribute(conv_kernel, cudaFuncAttributeMaxDynamicSharedMemorySize, 58624);

    init_kernel<<<1, 64>>>();

    dim3 cgrid(36, 4, 64), cblk(32, 8);
    conv_kernel<<<cgrid, cblk, 58624>>>(x, w);

    dim3 rgrid(277, 8);  // ceil(70688/256) x 8 batches
    gram_iter0_kernel<<<rgrid, 256>>>();
    iter1_kernel<<<rgrid, 256>>>();
    final_kernel<<<rgrid, 256>>>(out);
}